// round 1
// baseline (speedup 1.0000x reference)
#include <cuda_runtime.h>
#include <math.h>

#define BATCH 2
#define MP 40
#define MG 24
#define NPT 24
#define NRS 64
#define Hh 72
#define Ww 128
#define GRID_N (Hh*Ww)   // 9216
#define NPAIR (BATCH*MP*MG) // 1920
#define BIGF 1e9f
#define THICKF 0.03f
#define SHARPF 80.0f

// ---------------- device scratch (no allocs allowed) ----------------
__device__ float g_prs [BATCH*MP*NRS*2];
__device__ float g_grs [BATCH*MG*NRS*2];
__device__ float g_ptan[BATCH*MP*NRS*2];
__device__ float g_gtan[BATCH*MG*NRS*2];
__device__ float g_pmask[BATCH*MP*GRID_N];
__device__ float g_gmask[BATCH*MG*GRID_N];
__device__ float g_partial[NPAIR];
__device__ float g_inter[NPAIR];
__device__ float g_uni[NPAIR];

// ---------------- helpers ----------------
__device__ __forceinline__ float segdist(float qx, float qy,
                                         float ax, float ay,
                                         float bx, float by) {
    float abx = bx - ax, aby = by - ay;
    float dn  = fmaxf(abx*abx + aby*aby, 1e-8f);
    float t   = ((qx-ax)*abx + (qy-ay)*aby) / dn;
    t = fminf(fmaxf(t, 0.f), 1.f);
    float dx = qx - (ax + t*abx);
    float dy = qy - (ay + t*aby);
    return sqrtf(dx*dx + dy*dy);
}

__device__ __forceinline__ float sl1(float d) {
    d = fabsf(d);
    return d < 1.f ? 0.5f*d*d : d - 0.5f;
}

// ---------------- K1: mask-prep + arclength resample + tangents ----------------
// one block per curve (2*40 pred + 2*24 gt = 128 blocks), 64 threads
__global__ void k_resample(const float* __restrict__ pred,
                           const float* __restrict__ gt,
                           const float* __restrict__ vis) {
    int cid = blockIdx.x;
    int tid = threadIdx.x;
    __shared__ float px[NPT], py[NPT], pm[NPT], cum[NPT];
    __shared__ float ox[NRS], oy[NRS];

    bool isPred = cid < BATCH*MP;
    const float* src;
    float *dst_rs, *dst_tan;
    int b, c;
    if (isPred) {
        b = cid / MP; c = cid % MP;
        src = pred + (b*MP + c)*NPT*2;
        dst_rs  = g_prs  + (b*MP + c)*NRS*2;
        dst_tan = g_ptan + (b*MP + c)*NRS*2;
    } else {
        int q = cid - BATCH*MP;
        b = q / MG; c = q % MG;
        src = gt + (b*MG + c)*NPT*2;
        dst_rs  = g_grs  + (b*MG + c)*NRS*2;
        dst_tan = g_gtan + (b*MG + c)*NRS*2;
    }
    if (tid < NPT) {
        px[tid] = src[tid*2];
        py[tid] = src[tid*2+1];
        pm[tid] = isPred ? 1.0f : (vis[(b*MG+c)*NPT + tid] > 0.5f ? 1.0f : 0.0f);
    }
    __syncthreads();
    if (tid == 0) {
        if (!isPred) {
            int cnt = 0;
            for (int k = 0; k < NPT; k++) cnt += (pm[k] > 0.5f);
            if (cnt < 2) for (int k = 0; k < NPT; k++) pm[k] = 1.0f;  // fallback
        }
        float s = 0.f; cum[0] = 0.f;
        for (int k = 0; k < NPT-1; k++) {
            float dx = px[k+1]-px[k], dy = py[k+1]-py[k];
            float len = sqrtf(dx*dx+dy*dy) * (pm[k]*pm[k+1]);
            s += len; cum[k+1] = s;
        }
    }
    __syncthreads();
    float total = cum[NPT-1];
    float qx, qy;
    if (total < 1e-8f) { qx = px[0]; qy = py[0]; }
    else {
        float t = (tid == NRS-1) ? total : tid * (1.0f/(NRS-1)) * total;
        // searchsorted(cum, t, 'right') - 1  == (#cum <= t) - 1
        int cnt = 0;
        for (int k = 0; k < NPT; k++) cnt += (cum[k] <= t);
        int idx = cnt - 1;
        if (idx > NPT-2) idx = NPT-2;
        if (idx < 0)     idx = 0;
        float lt = cum[idx], rt = cum[idx+1];
        float alpha = (t - lt) / fmaxf(rt - lt, 1e-8f);
        qx = px[idx] + alpha*(px[idx+1]-px[idx]);
        qy = py[idx] + alpha*(py[idx+1]-py[idx]);
    }
    ox[tid] = qx; oy[tid] = qy;
    dst_rs[tid*2]   = qx;
    dst_rs[tid*2+1] = qy;
    __syncthreads();
    // central-difference tangents
    int a = (tid == 0)     ? 0     : tid-1;
    int e = (tid == NRS-1) ? NRS-1 : tid+1;
    float fx = ox[e]-ox[a], fy = oy[e]-oy[a];
    float nr = fmaxf(sqrtf(fx*fx+fy*fy), 1e-8f);
    dst_tan[tid*2]   = fx/nr;
    dst_tan[tid*2+1] = fy/nr;
}

// ---------------- K2: pairwise sym / tangent / curvature ----------------
// one block per (b,i,j) pair = 1920 blocks, 64 threads
__global__ void k_pair() {
    int pid = blockIdx.x;
    int b = pid / (MP*MG);
    int r = pid % (MP*MG);
    int i = r / MG, j = r % MG;
    int n = threadIdx.x;

    __shared__ float ppx[NRS], ppy[NRS], gpx[NRS], gpy[NRS];
    __shared__ float ptx[NRS], pty[NRS], gtx[NRS], gty[NRS];

    const float* pr  = g_prs  + (b*MP+i)*NRS*2;
    const float* gr  = g_grs  + (b*MG+j)*NRS*2;
    const float* pt  = g_ptan + (b*MP+i)*NRS*2;
    const float* gt2 = g_gtan + (b*MG+j)*NRS*2;
    ppx[n] = pr[2*n];  ppy[n] = pr[2*n+1];
    gpx[n] = gr[2*n];  gpy[n] = gr[2*n+1];
    ptx[n] = pt[2*n];  pty[n] = pt[2*n+1];
    gtx[n] = gt2[2*n]; gty[n] = gt2[2*n+1];
    __syncthreads();

    float da = BIGF, db = BIGF;
    float qx = ppx[n], qy = ppy[n], ux = gpx[n], uy = gpy[n];
    #pragma unroll 7
    for (int s = 0; s < NRS-1; s++) {
        da = fminf(da, segdist(qx, qy, gpx[s], gpy[s], gpx[s+1], gpy[s+1]));
        db = fminf(db, segdist(ux, uy, ppx[s], ppy[s], ppx[s+1], ppy[s+1]));
    }
    float td = fabsf(ptx[n]*gtx[n] + pty[n]*gty[n]);
    float cv = 0.f;
    if (n < NRS-2) {
        float psx = ppx[n+2] - 2.f*ppx[n+1] + ppx[n];
        float psy = ppy[n+2] - 2.f*ppy[n+1] + ppy[n];
        float gsx = gpx[n+2] - 2.f*gpx[n+1] + gpx[n];
        float gsy = gpy[n+2] - 2.f*gpy[n+1] + gpy[n];
        cv = sl1(psx-gsx) + sl1(psy-gsy);
    }
    // 64-thread reduce: warp shuffles + 2-warp combine
    unsigned m = 0xffffffffu;
    #pragma unroll
    for (int o = 16; o; o >>= 1) {
        da += __shfl_down_sync(m, da, o);
        db += __shfl_down_sync(m, db, o);
        td += __shfl_down_sync(m, td, o);
        cv += __shfl_down_sync(m, cv, o);
    }
    __shared__ float red[2][4];
    int w = n >> 5, l = n & 31;
    if (l == 0) { red[w][0]=da; red[w][1]=db; red[w][2]=td; red[w][3]=cv; }
    __syncthreads();
    if (n == 0) {
        float sda  = red[0][0] + red[1][0];
        float sdb  = red[0][1] + red[1][1];
        float stda = red[0][2] + red[1][2];
        float scv  = red[0][3] + red[1][3];
        float sym  = 0.5f * (sda + sdb) * (1.0f/NRS);
        float tanv = 1.0f - stda * (1.0f/NRS);
        float curv = scv * (1.0f/((NRS-2)*2));
        g_partial[pid] = 5.0f*sym + 1.0f*tanv + 0.5f*curv;
        g_inter[pid] = 0.f;   // zero accumulators for K4 (stream-ordered)
        g_uni[pid]   = 0.f;
    }
}

// ---------------- K3: soft occupancy masks on the raw 24-pt curves ----------------
// grid: (128 curves, 4 chunks), 256 threads; each thread -> 9 grid points
__global__ void k_mask(const float* __restrict__ pred,
                       const float* __restrict__ gt,
                       const float* __restrict__ vis) {
    int cid = blockIdx.x;
    int chunk = blockIdx.y;
    int tid = threadIdx.x;
    __shared__ float px[NPT], py[NPT], pm[NPT];
    __shared__ float sax[NPT-1], say[NPT-1], sabx[NPT-1], saby[NPT-1], sdn[NPT-1];
    __shared__ int   svalid[NPT-1];
    __shared__ int   s_any;

    bool isPred = cid < BATCH*MP;
    const float* src;
    float* dst;
    int b, c;
    if (isPred) {
        b = cid/MP; c = cid%MP;
        src = pred + (b*MP+c)*NPT*2;
        dst = g_pmask + (b*MP+c)*GRID_N;
    } else {
        int q = cid - BATCH*MP;
        b = q/MG; c = q%MG;
        src = gt + (b*MG+c)*NPT*2;
        dst = g_gmask + (b*MG+c)*GRID_N;
    }
    if (tid < NPT) {
        px[tid] = src[tid*2];
        py[tid] = src[tid*2+1];
        pm[tid] = isPred ? 1.f : (vis[(b*MG+c)*NPT+tid] > 0.5f ? 1.f : 0.f);
    }
    __syncthreads();
    if (tid == 0) {
        if (!isPred) {
            int cnt = 0;
            for (int k = 0; k < NPT; k++) cnt += (pm[k] > 0.5f);
            if (cnt < 2) for (int k = 0; k < NPT; k++) pm[k] = 1.f;
        }
        int any = 0;
        for (int k = 0; k < NPT-1; k++) any |= (pm[k]*pm[k+1] > 0.5f);
        s_any = any;
    }
    __syncthreads();
    if (tid < NPT-1) {
        float abx = px[tid+1]-px[tid], aby = py[tid+1]-py[tid];
        sax[tid]=px[tid]; say[tid]=py[tid];
        sabx[tid]=abx;    saby[tid]=aby;
        sdn[tid] = fmaxf(abx*abx + aby*aby, 1e-8f);
        svalid[tid] = (pm[tid]*pm[tid+1] > 0.5f);
    }
    __syncthreads();

    const int CH = GRID_N/4;  // 2304
    int any = s_any;
    for (int g = chunk*CH + tid; g < (chunk+1)*CH; g += blockDim.x) {
        int gy = g / Ww, gx = g % Ww;
        float X = gx * (1.0f/(Ww-1));
        float Y = gy * (1.0f/(Hh-1));
        float mind = BIGF;
        if (any) {
            #pragma unroll
            for (int s = 0; s < NPT-1; s++) {
                if (!svalid[s]) continue;
                float t = ((X-sax[s])*sabx[s] + (Y-say[s])*saby[s]) / sdn[s];
                t = fminf(fmaxf(t, 0.f), 1.f);
                float dx = X - (sax[s] + t*sabx[s]);
                float dy = Y - (say[s] + t*saby[s]);
                mind = fminf(mind, sqrtf(dx*dx + dy*dy));
            }
        } else {
            #pragma unroll
            for (int k = 0; k < NPT; k++) {
                if (pm[k] > 0.5f) {
                    float dx = X-px[k], dy = Y-py[k];
                    mind = fminf(mind, sqrtf(dx*dx + dy*dy));
                }
            }
        }
        float z = (THICKF - mind) * SHARPF;
        dst[g] = 1.0f / (1.0f + expf(-z));
    }
}

// ---------------- K4: pairwise IoU accumulation over grid chunks ----------------
// one block per (b, chunk-of-128 grid pts) = 144 blocks, 256 threads
__global__ void k_overlap() {
    __shared__ float sm[128*65];  // [g][curve], padded to 65 -> conflict-free
    int blk = blockIdx.x;
    int b  = blk / (GRID_N/128);
    int ch = blk % (GRID_N/128);
    int gbase = ch * 128;
    int tid = threadIdx.x;

    for (int idx = tid; idx < 64*128; idx += 256) {
        int c = idx >> 7, g = idx & 127;   // consecutive tid -> consecutive g (coalesced)
        float v = (c < MP) ? g_pmask[(b*MP + c)*GRID_N + gbase + g]
                           : g_gmask[(b*MG + (c-MP))*GRID_N + gbase + g];
        sm[g*65 + c] = v;
    }
    __syncthreads();

    for (int p = tid; p < MP*MG; p += 256) {
        int i = p / MG, j = p % MG;
        float si = 0.f, su = 0.f;
        #pragma unroll 8
        for (int g = 0; g < 128; g++) {
            float a  = sm[g*65 + i];
            float bb = sm[g*65 + MP + j];
            si += fminf(a, bb);
            su += fmaxf(a, bb);
        }
        atomicAdd(&g_inter[b*MP*MG + p], si);
        atomicAdd(&g_uni  [b*MP*MG + p], su);
    }
}

// ---------------- K5: combine + exist mask ----------------
__global__ void k_final(const float* __restrict__ exist, float* __restrict__ out) {
    int p = blockIdx.x*256 + threadIdx.x;
    if (p < NPAIR) {
        int b = p / (MP*MG);
        int j = p % MG;
        float ov = 1.0f - g_inter[p] / (g_uni[p] + 1e-8f);
        float cost = g_partial[p] + 2.0f*ov;
        out[p] = (exist[b*MG + j] > 0.5f) ? cost : 0.0f;
    }
}

// ---------------- launch ----------------
extern "C" void kernel_launch(void* const* d_in, const int* in_sizes, int n_in,
                              void* d_out, int out_size) {
    const float* pred  = (const float*)d_in[0];  // (2,40,24,2)
    const float* gt    = (const float*)d_in[1];  // (2,24,24,2)
    const float* vis   = (const float*)d_in[2];  // (2,24,24)
    const float* exist = (const float*)d_in[3];  // (2,24)
    float* out = (float*)d_out;                  // (2,40,24)

    k_resample<<<BATCH*(MP+MG), NRS>>>(pred, gt, vis);
    k_pair    <<<NPAIR, NRS>>>();
    k_mask    <<<dim3(BATCH*(MP+MG), 4), 256>>>(pred, gt, vis);
    k_overlap <<<BATCH*(GRID_N/128), 256>>>();
    k_final   <<<(NPAIR + 255)/256, 256>>>(exist, out);
}

// round 2
// speedup vs baseline: 2.3063x; 2.3063x over previous
#include <cuda_runtime.h>
#include <math.h>

#define BATCH 2
#define MP 40
#define MG 24
#define NPT 24
#define NRS 64
#define Hh 72
#define Ww 128
#define GRID_N (Hh*Ww)      // 9216
#define NPAIR (BATCH*MP*MG) // 1920
#define BIGF 1e9f
#define BIG2 1e18f
#define THICKF 0.03f
#define SHARPF 80.0f

// ---------------- device scratch ----------------
__device__ float g_prs [BATCH*MP*NRS*2];
__device__ float g_grs [BATCH*MG*NRS*2];
__device__ float g_ptan[BATCH*MP*NRS*2];
__device__ float g_gtan[BATCH*MG*NRS*2];
__device__ float g_pmask[BATCH*MP*GRID_N];
__device__ float g_gmask[BATCH*MG*GRID_N];
__device__ float g_partial[NPAIR];
__device__ float g_inter[NPAIR];
__device__ float g_uni[NPAIR];

__device__ __forceinline__ float sl1(float d) {
    d = fabsf(d);
    return d < 1.f ? 0.5f*d*d : d - 0.5f;
}

// =====================================================================
// Kernel A: [blocks 0..127]   resample + tangents (one curve per block)
//           [blocks 128..639] soft masks (curve cid, grid chunk of 2304)
//           also zeroes the inter/union accumulators
// =====================================================================
__global__ void k_A(const float* __restrict__ pred,
                    const float* __restrict__ gt,
                    const float* __restrict__ vis) {
    int bid = blockIdx.x, tid = threadIdx.x;
    int gtid = bid*256 + tid;
    if (gtid < NPAIR) { g_inter[gtid] = 0.f; g_uni[gtid] = 0.f; }

    if (bid < 128) {
        // ---------------- resample ----------------
        __shared__ float px[NPT], py[NPT], pm[NPT], cum[NPT];
        __shared__ float ox[NRS], oy[NRS];
        int cid = bid;
        bool isPred = cid < BATCH*MP;
        const float* src; float *dst_rs, *dst_tan; int b, c;
        if (isPred) {
            b = cid / MP; c = cid % MP;
            src = pred + (b*MP + c)*NPT*2;
            dst_rs  = g_prs  + (b*MP + c)*NRS*2;
            dst_tan = g_ptan + (b*MP + c)*NRS*2;
        } else {
            int q = cid - BATCH*MP;
            b = q / MG; c = q % MG;
            src = gt + (b*MG + c)*NPT*2;
            dst_rs  = g_grs  + (b*MG + c)*NRS*2;
            dst_tan = g_gtan + (b*MG + c)*NRS*2;
        }
        if (tid < NPT) {
            px[tid] = src[tid*2];
            py[tid] = src[tid*2+1];
            pm[tid] = isPred ? 1.0f : (vis[(b*MG+c)*NPT + tid] > 0.5f ? 1.0f : 0.0f);
        }
        __syncthreads();
        if (tid == 0) {
            if (!isPred) {
                int cnt = 0;
                for (int k = 0; k < NPT; k++) cnt += (pm[k] > 0.5f);
                if (cnt < 2) for (int k = 0; k < NPT; k++) pm[k] = 1.0f;
            }
            float s = 0.f; cum[0] = 0.f;
            for (int k = 0; k < NPT-1; k++) {
                float dx = px[k+1]-px[k], dy = py[k+1]-py[k];
                s += sqrtf(dx*dx+dy*dy) * (pm[k]*pm[k+1]);
                cum[k+1] = s;
            }
        }
        __syncthreads();
        if (tid < NRS) {
            float total = cum[NPT-1];
            float qx, qy;
            if (total < 1e-8f) { qx = px[0]; qy = py[0]; }
            else {
                float t = (tid == NRS-1) ? total : tid * (1.0f/(NRS-1)) * total;
                int cnt = 0;
                for (int k = 0; k < NPT; k++) cnt += (cum[k] <= t);
                int idx = cnt - 1;
                if (idx > NPT-2) idx = NPT-2;
                if (idx < 0)     idx = 0;
                float lt = cum[idx], rt = cum[idx+1];
                float alpha = (t - lt) / fmaxf(rt - lt, 1e-8f);
                qx = px[idx] + alpha*(px[idx+1]-px[idx]);
                qy = py[idx] + alpha*(py[idx+1]-py[idx]);
            }
            ox[tid] = qx; oy[tid] = qy;
            dst_rs[tid*2]   = qx;
            dst_rs[tid*2+1] = qy;
        }
        __syncthreads();
        if (tid < NRS) {
            int a = (tid == 0)     ? 0     : tid-1;
            int e = (tid == NRS-1) ? NRS-1 : tid+1;
            float fx = ox[e]-ox[a], fy = oy[e]-oy[a];
            float nr = fmaxf(sqrtf(fx*fx+fy*fy), 1e-8f);
            dst_tan[tid*2]   = fx/nr;
            dst_tan[tid*2+1] = fy/nr;
        }
    } else {
        // ---------------- soft mask ----------------
        int mb = bid - 128;
        int cid = mb >> 2, chunk = mb & 3;
        __shared__ float px[NPT], py[NPT], pm[NPT], sppen[NPT];
        __shared__ float sax[NPT-1], say[NPT-1], sabx[NPT-1], saby[NPT-1];
        __shared__ float sinv[NPT-1], spen[NPT-1];
        __shared__ int s_any;

        bool isPred = cid < BATCH*MP;
        const float* src; float* dst; int b, c;
        if (isPred) {
            b = cid/MP; c = cid%MP;
            src = pred + (b*MP+c)*NPT*2;
            dst = g_pmask + (b*MP+c)*GRID_N;
        } else {
            int q = cid - BATCH*MP;
            b = q/MG; c = q%MG;
            src = gt + (b*MG+c)*NPT*2;
            dst = g_gmask + (b*MG+c)*GRID_N;
        }
        if (tid < NPT) {
            px[tid] = src[tid*2];
            py[tid] = src[tid*2+1];
            pm[tid] = isPred ? 1.f : (vis[(b*MG+c)*NPT+tid] > 0.5f ? 1.f : 0.f);
        }
        __syncthreads();
        if (tid == 0) {
            if (!isPred) {
                int cnt = 0;
                for (int k = 0; k < NPT; k++) cnt += (pm[k] > 0.5f);
                if (cnt < 2) for (int k = 0; k < NPT; k++) pm[k] = 1.f;
            }
            int any = 0;
            for (int k = 0; k < NPT-1; k++) any |= (pm[k]*pm[k+1] > 0.5f);
            s_any = any;
        }
        __syncthreads();
        if (tid < NPT-1) {
            float abx = px[tid+1]-px[tid], aby = py[tid+1]-py[tid];
            sax[tid]=px[tid]; say[tid]=py[tid];
            sabx[tid]=abx;    saby[tid]=aby;
            sinv[tid] = 1.0f / fmaxf(abx*abx + aby*aby, 1e-8f);
            spen[tid] = (pm[tid]*pm[tid+1] > 0.5f) ? 0.f : BIG2;
        }
        if (tid < NPT) sppen[tid] = (pm[tid] > 0.5f) ? 0.f : BIG2;
        __syncthreads();

        const int CH = GRID_N/4;  // 2304
        int any = s_any;
        for (int g = chunk*CH + tid; g < (chunk+1)*CH; g += 256) {
            int gy = g / Ww, gx = g % Ww;
            float X = gx * (1.0f/(Ww-1));
            float Y = gy * (1.0f/(Hh-1));
            float mind2 = BIG2;
            if (any) {
                #pragma unroll
                for (int s = 0; s < NPT-1; s++) {
                    float t = ((X-sax[s])*sabx[s] + (Y-say[s])*saby[s]) * sinv[s];
                    t = fminf(fmaxf(t, 0.f), 1.f);
                    float dx = X - sax[s] - t*sabx[s];
                    float dy = Y - say[s] - t*saby[s];
                    mind2 = fminf(mind2, dx*dx + dy*dy + spen[s]);
                }
            } else {
                #pragma unroll
                for (int k = 0; k < NPT; k++) {
                    float dx = X-px[k], dy = Y-py[k];
                    mind2 = fminf(mind2, dx*dx + dy*dy + sppen[k]);
                }
            }
            float z = (THICKF - sqrtf(mind2)) * SHARPF;
            dst[g] = 1.0f / (1.0f + __expf(-z));
        }
    }
}

// =====================================================================
// Kernel B: [blocks 0..479]   pairwise sym/tan/curv (4 pairs per block)
//           [blocks 480..767] IoU accumulation over 64-pt grid chunks
// =====================================================================
#define GSTRIDE 392
__global__ void k_B() {
    __shared__ __align__(16) float sm[64*68];   // 17408 B, reused by both halves
    int bid = blockIdx.x, tid = threadIdx.x;

    if (bid < 480) {
        // ---------------- pair costs ----------------
        int grp = tid >> 6, n = tid & 63;
        int pid = bid*4 + grp;
        int b = pid / (MP*MG);
        int r = pid % (MP*MG);
        int i = r / MG, j = r % MG;

        float* gp   = sm + grp*GSTRIDE;
        float* spx  = gp;        float* spy  = gp + 64;
        float* sgx  = gp + 128;  float* sgy  = gp + 192;
        float* spinv= gp + 256;  float* sginv= gp + 319;
        float* red  = gp + 382;  // 6 floats

        const float* pr = g_prs + (b*MP+i)*NRS*2;
        const float* gr = g_grs + (b*MG+j)*NRS*2;
        spx[n] = pr[2*n]; spy[n] = pr[2*n+1];
        sgx[n] = gr[2*n]; sgy[n] = gr[2*n+1];
        __syncthreads();
        if (n < NRS-1) {
            float dx = spx[n+1]-spx[n], dy = spy[n+1]-spy[n];
            spinv[n] = 1.0f / fmaxf(dx*dx+dy*dy, 1e-8f);
            dx = sgx[n+1]-sgx[n]; dy = sgy[n+1]-sgy[n];
            sginv[n] = 1.0f / fmaxf(dx*dx+dy*dy, 1e-8f);
        }
        __syncthreads();

        float qx = spx[n], qy = spy[n], ux = sgx[n], uy = sgy[n];
        float da2 = BIG2, db2 = BIG2;
        #pragma unroll 9
        for (int s = 0; s < NRS-1; s++) {
            {
                float ax = sgx[s], ay = sgy[s];
                float abx = sgx[s+1]-ax, aby = sgy[s+1]-ay;
                float t = ((qx-ax)*abx + (qy-ay)*aby) * sginv[s];
                t = fminf(fmaxf(t, 0.f), 1.f);
                float dx = qx - ax - t*abx, dy = qy - ay - t*aby;
                da2 = fminf(da2, dx*dx + dy*dy);
            }
            {
                float ax = spx[s], ay = spy[s];
                float abx = spx[s+1]-ax, aby = spy[s+1]-ay;
                float t = ((ux-ax)*abx + (uy-ay)*aby) * spinv[s];
                t = fminf(fmaxf(t, 0.f), 1.f);
                float dx = ux - ax - t*abx, dy = uy - ay - t*aby;
                db2 = fminf(db2, dx*dx + dy*dy);
            }
        }
        float dd = sqrtf(da2) + sqrtf(db2);

        const float* pt  = g_ptan + (b*MP+i)*NRS*2;
        const float* gtt = g_gtan + (b*MG+j)*NRS*2;
        float td = fabsf(pt[2*n]*gtt[2*n] + pt[2*n+1]*gtt[2*n+1]);

        float cv = 0.f;
        if (n < NRS-2) {
            float psx = spx[n+2] - 2.f*spx[n+1] + spx[n];
            float psy = spy[n+2] - 2.f*spy[n+1] + spy[n];
            float gsx = sgx[n+2] - 2.f*sgx[n+1] + sgx[n];
            float gsy = sgy[n+2] - 2.f*sgy[n+1] + sgy[n];
            cv = sl1(psx-gsx) + sl1(psy-gsy);
        }
        unsigned m = 0xffffffffu;
        #pragma unroll
        for (int o = 16; o; o >>= 1) {
            dd += __shfl_down_sync(m, dd, o);
            td += __shfl_down_sync(m, td, o);
            cv += __shfl_down_sync(m, cv, o);
        }
        int w = (n >> 5), l = n & 31;
        if (l == 0) { red[w*3+0]=dd; red[w*3+1]=td; red[w*3+2]=cv; }
        __syncthreads();
        if (n == 0) {
            float sdd = red[0] + red[3];
            float std_ = red[1] + red[4];
            float scv = red[2] + red[5];
            float sym  = 0.5f * sdd * (1.0f/NRS);
            float tanv = 1.0f - std_ * (1.0f/NRS);
            float curv = scv * (1.0f/((NRS-2)*2));
            g_partial[pid] = 5.0f*sym + 1.0f*tanv + 0.5f*curv;
        }
    } else {
        // ---------------- IoU over grid chunk ----------------
        int blk = bid - 480;
        int b  = blk / 144;
        int ch = blk % 144;
        int gbase = ch * 64;

        for (int idx = tid; idx < 64*64; idx += 256) {
            int c = idx >> 6, g = idx & 63;
            float v = (c < MP) ? g_pmask[(b*MP + c)*GRID_N + gbase + g]
                               : g_gmask[(b*MG + (c-MP))*GRID_N + gbase + g];
            sm[c*68 + g] = v;
        }
        __syncthreads();

        for (int p = tid; p < MP*MG; p += 256) {
            int i = p / MG, j = p % MG;
            const float4* ar = (const float4*)(sm + i*68);
            const float4* br = (const float4*)(sm + (MP+j)*68);
            float si = 0.f, su = 0.f;
            #pragma unroll
            for (int q = 0; q < 16; q++) {
                float4 a = ar[q], bb = br[q];
                si += fminf(a.x,bb.x) + fminf(a.y,bb.y) + fminf(a.z,bb.z) + fminf(a.w,bb.w);
                su += fmaxf(a.x,bb.x) + fmaxf(a.y,bb.y) + fmaxf(a.z,bb.z) + fmaxf(a.w,bb.w);
            }
            atomicAdd(&g_inter[b*MP*MG + p], si);
            atomicAdd(&g_uni  [b*MP*MG + p], su);
        }
    }
}

// =====================================================================
// Kernel C: combine + exist mask
// =====================================================================
__global__ void k_final(const float* __restrict__ exist, float* __restrict__ out) {
    int p = blockIdx.x*256 + threadIdx.x;
    if (p < NPAIR) {
        int b = p / (MP*MG);
        int j = p % MG;
        float ov = 1.0f - g_inter[p] / (g_uni[p] + 1e-8f);
        float cost = g_partial[p] + 2.0f*ov;
        out[p] = (exist[b*MG + j] > 0.5f) ? cost : 0.0f;
    }
}

// ---------------- launch ----------------
extern "C" void kernel_launch(void* const* d_in, const int* in_sizes, int n_in,
                              void* d_out, int out_size) {
    const float* pred  = (const float*)d_in[0];
    const float* gt    = (const float*)d_in[1];
    const float* vis   = (const float*)d_in[2];
    const float* exist = (const float*)d_in[3];
    float* out = (float*)d_out;

    k_A<<<640, 256>>>(pred, gt, vis);
    k_B<<<768, 256>>>();
    k_final<<<(NPAIR + 255)/256, 256>>>(exist, out);
}

// round 3
// speedup vs baseline: 2.8003x; 1.2142x over previous
#include <cuda_runtime.h>
#include <math.h>

#define BATCH 2
#define MP 40
#define MG 24
#define NPT 24
#define NRS 64
#define Hh 72
#define Ww 128
#define GRID_N (Hh*Ww)      // 9216
#define NPAIR (BATCH*MP*MG) // 1920
#define BIG2 1e18f
#define THICKF 0.03f
#define SHARPF 80.0f

// ---------------- device scratch ----------------
__device__ float g_prs [BATCH*MP*NRS*2];
__device__ float g_grs [BATCH*MG*NRS*2];
__device__ float g_ptan[BATCH*MP*NRS*2];
__device__ float g_gtan[BATCH*MG*NRS*2];
__device__ float g_pmask[BATCH*MP*GRID_N];
__device__ float g_gmask[BATCH*MG*GRID_N];
__device__ float g_partial[NPAIR];
__device__ float g_inter[NPAIR];
__device__ float g_uni[NPAIR];

__device__ __forceinline__ float sl1(float d) {
    d = fabsf(d);
    return d < 1.f ? 0.5f*d*d : d - 0.5f;
}

// =====================================================================
// Kernel A: [blocks 0..127]    resample + tangents (one curve per block)
//           [blocks 128..1279] soft masks: curve = (bid-128)/9,
//                              chunk of 1024 grid pts, 4 pts per thread
//           also zeroes the inter/union accumulators
// =====================================================================
__global__ void __launch_bounds__(256, 4)
k_A(const float* __restrict__ pred,
    const float* __restrict__ gt,
    const float* __restrict__ vis) {
    int bid = blockIdx.x, tid = threadIdx.x;
    int gtid = bid*256 + tid;
    if (gtid < NPAIR) { g_inter[gtid] = 0.f; g_uni[gtid] = 0.f; }

    if (bid < 128) {
        // ---------------- resample + tangents ----------------
        __shared__ float px[NPT], py[NPT], pm[NPT], cum[NPT];
        __shared__ float ox[NRS], oy[NRS];
        int cid = bid;
        bool isPred = cid < BATCH*MP;
        const float* src; float *dst_rs, *dst_tan; int b, c;
        if (isPred) {
            b = cid / MP; c = cid % MP;
            src = pred + (b*MP + c)*NPT*2;
            dst_rs  = g_prs  + (b*MP + c)*NRS*2;
            dst_tan = g_ptan + (b*MP + c)*NRS*2;
        } else {
            int q = cid - BATCH*MP;
            b = q / MG; c = q % MG;
            src = gt + (b*MG + c)*NPT*2;
            dst_rs  = g_grs  + (b*MG + c)*NRS*2;
            dst_tan = g_gtan + (b*MG + c)*NRS*2;
        }
        if (tid < NPT) {
            px[tid] = src[tid*2];
            py[tid] = src[tid*2+1];
            pm[tid] = isPred ? 1.0f : (vis[(b*MG+c)*NPT + tid] > 0.5f ? 1.0f : 0.0f);
        }
        __syncthreads();
        if (tid == 0) {
            if (!isPred) {
                int cnt = 0;
                for (int k = 0; k < NPT; k++) cnt += (pm[k] > 0.5f);
                if (cnt < 2) for (int k = 0; k < NPT; k++) pm[k] = 1.0f;
            }
            float s = 0.f; cum[0] = 0.f;
            for (int k = 0; k < NPT-1; k++) {
                float dx = px[k+1]-px[k], dy = py[k+1]-py[k];
                s += sqrtf(dx*dx+dy*dy) * (pm[k]*pm[k+1]);
                cum[k+1] = s;
            }
        }
        __syncthreads();
        if (tid < NRS) {
            float total = cum[NPT-1];
            float qx, qy;
            if (total < 1e-8f) { qx = px[0]; qy = py[0]; }
            else {
                float t = (tid == NRS-1) ? total : tid * (1.0f/(NRS-1)) * total;
                int cnt = 0;
                for (int k = 0; k < NPT; k++) cnt += (cum[k] <= t);
                int idx = cnt - 1;
                if (idx > NPT-2) idx = NPT-2;
                if (idx < 0)     idx = 0;
                float lt = cum[idx], rt = cum[idx+1];
                float alpha = (t - lt) / fmaxf(rt - lt, 1e-8f);
                qx = px[idx] + alpha*(px[idx+1]-px[idx]);
                qy = py[idx] + alpha*(py[idx+1]-py[idx]);
            }
            ox[tid] = qx; oy[tid] = qy;
            dst_rs[tid*2]   = qx;
            dst_rs[tid*2+1] = qy;
        }
        __syncthreads();
        if (tid < NRS) {
            int a = (tid == 0)     ? 0     : tid-1;
            int e = (tid == NRS-1) ? NRS-1 : tid+1;
            float fx = ox[e]-ox[a], fy = oy[e]-oy[a];
            float nr = fmaxf(sqrtf(fx*fx+fy*fy), 1e-8f);
            dst_tan[tid*2]   = fx/nr;
            dst_tan[tid*2+1] = fy/nr;
        }
    } else {
        // ---------------- soft mask: 4 grid points per thread ----------------
        int mb = bid - 128;
        int cid = mb / 9, chunk = mb % 9;
        __shared__ float px[NPT], py[NPT], pm[NPT], sppen[NPT];
        __shared__ float sax[NPT-1], say[NPT-1], sabx[NPT-1], saby[NPT-1];
        __shared__ float sinv[NPT-1], spen[NPT-1];
        __shared__ int s_any;

        bool isPred = cid < BATCH*MP;
        const float* src; float* dst; int b, c;
        if (isPred) {
            b = cid/MP; c = cid%MP;
            src = pred + (b*MP+c)*NPT*2;
            dst = g_pmask + (b*MP+c)*GRID_N;
        } else {
            int q = cid - BATCH*MP;
            b = q/MG; c = q%MG;
            src = gt + (b*MG+c)*NPT*2;
            dst = g_gmask + (b*MG+c)*GRID_N;
        }
        if (tid < NPT) {
            px[tid] = src[tid*2];
            py[tid] = src[tid*2+1];
            pm[tid] = isPred ? 1.f : (vis[(b*MG+c)*NPT+tid] > 0.5f ? 1.f : 0.f);
        }
        __syncthreads();
        if (tid == 0) {
            if (!isPred) {
                int cnt = 0;
                for (int k = 0; k < NPT; k++) cnt += (pm[k] > 0.5f);
                if (cnt < 2) for (int k = 0; k < NPT; k++) pm[k] = 1.f;
            }
            int any = 0;
            for (int k = 0; k < NPT-1; k++) any |= (pm[k]*pm[k+1] > 0.5f);
            s_any = any;
        }
        __syncthreads();
        if (tid < NPT-1) {
            float abx = px[tid+1]-px[tid], aby = py[tid+1]-py[tid];
            sax[tid]=px[tid]; say[tid]=py[tid];
            sabx[tid]=abx;    saby[tid]=aby;
            sinv[tid] = 1.0f / fmaxf(abx*abx + aby*aby, 1e-8f);
            spen[tid] = (pm[tid]*pm[tid+1] > 0.5f) ? 0.f : BIG2;
        }
        if (tid < NPT) sppen[tid] = (pm[tid] > 0.5f) ? 0.f : BIG2;
        __syncthreads();

        int base = chunk*1024 + tid;
        float X0, Y0, X1, Y1, X2, Y2, X3, Y3;
        {
            int g0 = base, g1 = base+256, g2 = base+512, g3 = base+768;
            X0 = (g0 & 127) * (1.0f/(Ww-1)); Y0 = (g0 >> 7) * (1.0f/(Hh-1));
            X1 = (g1 & 127) * (1.0f/(Ww-1)); Y1 = (g1 >> 7) * (1.0f/(Hh-1));
            X2 = (g2 & 127) * (1.0f/(Ww-1)); Y2 = (g2 >> 7) * (1.0f/(Hh-1));
            X3 = (g3 & 127) * (1.0f/(Ww-1)); Y3 = (g3 >> 7) * (1.0f/(Hh-1));
        }
        float m0 = BIG2, m1 = BIG2, m2 = BIG2, m3 = BIG2;
        if (s_any) {
            #pragma unroll 1
            for (int s = 0; s < NPT-1; s++) {
                float ax = sax[s], ay = say[s];
                float abx = sabx[s], aby = saby[s];
                float inv = sinv[s], pen = spen[s];
                {
                    float t = ((X0-ax)*abx + (Y0-ay)*aby) * inv;
                    t = fminf(fmaxf(t, 0.f), 1.f);
                    float dx = X0 - ax - t*abx, dy = Y0 - ay - t*aby;
                    m0 = fminf(m0, dx*dx + dy*dy + pen);
                }
                {
                    float t = ((X1-ax)*abx + (Y1-ay)*aby) * inv;
                    t = fminf(fmaxf(t, 0.f), 1.f);
                    float dx = X1 - ax - t*abx, dy = Y1 - ay - t*aby;
                    m1 = fminf(m1, dx*dx + dy*dy + pen);
                }
                {
                    float t = ((X2-ax)*abx + (Y2-ay)*aby) * inv;
                    t = fminf(fmaxf(t, 0.f), 1.f);
                    float dx = X2 - ax - t*abx, dy = Y2 - ay - t*aby;
                    m2 = fminf(m2, dx*dx + dy*dy + pen);
                }
                {
                    float t = ((X3-ax)*abx + (Y3-ay)*aby) * inv;
                    t = fminf(fmaxf(t, 0.f), 1.f);
                    float dx = X3 - ax - t*abx, dy = Y3 - ay - t*aby;
                    m3 = fminf(m3, dx*dx + dy*dy + pen);
                }
            }
        } else {
            #pragma unroll 1
            for (int k = 0; k < NPT; k++) {
                float ax = px[k], ay = py[k], pen = sppen[k];
                float dx, dy;
                dx = X0-ax; dy = Y0-ay; m0 = fminf(m0, dx*dx + dy*dy + pen);
                dx = X1-ax; dy = Y1-ay; m1 = fminf(m1, dx*dx + dy*dy + pen);
                dx = X2-ax; dy = Y2-ay; m2 = fminf(m2, dx*dx + dy*dy + pen);
                dx = X3-ax; dy = Y3-ay; m3 = fminf(m3, dx*dx + dy*dy + pen);
            }
        }
        dst[base      ] = __fdividef(1.0f, 1.0f + __expf(-(THICKF - sqrtf(m0)) * SHARPF));
        dst[base + 256] = __fdividef(1.0f, 1.0f + __expf(-(THICKF - sqrtf(m1)) * SHARPF));
        dst[base + 512] = __fdividef(1.0f, 1.0f + __expf(-(THICKF - sqrtf(m2)) * SHARPF));
        dst[base + 768] = __fdividef(1.0f, 1.0f + __expf(-(THICKF - sqrtf(m3)) * SHARPF));
    }
}

// =====================================================================
// Kernel B: [blocks 0..479]   pairwise sym/tan/curv (4 pairs per block)
//           [blocks 480..767] IoU accumulation over 64-pt grid chunks
// =====================================================================
#define GSTRIDE 392
__global__ void __launch_bounds__(256, 4)
k_B() {
    __shared__ __align__(16) float sm[64*68];   // 17408 B
    int bid = blockIdx.x, tid = threadIdx.x;

    if (bid < 480) {
        // ---------------- pair costs ----------------
        int grp = tid >> 6, n = tid & 63;
        int pid = bid*4 + grp;
        int b = pid / (MP*MG);
        int r = pid % (MP*MG);
        int i = r / MG, j = r % MG;

        float* gp   = sm + grp*GSTRIDE;
        float* spx  = gp;        float* spy  = gp + 64;
        float* sgx  = gp + 128;  float* sgy  = gp + 192;
        float* spinv= gp + 256;  float* sginv= gp + 319;
        float* red  = gp + 382;  // 6 floats

        const float* pr = g_prs + (b*MP+i)*NRS*2;
        const float* gr = g_grs + (b*MG+j)*NRS*2;
        spx[n] = pr[2*n]; spy[n] = pr[2*n+1];
        sgx[n] = gr[2*n]; sgy[n] = gr[2*n+1];
        __syncthreads();
        if (n < NRS-1) {
            float dx = spx[n+1]-spx[n], dy = spy[n+1]-spy[n];
            spinv[n] = 1.0f / fmaxf(dx*dx+dy*dy, 1e-8f);
            dx = sgx[n+1]-sgx[n]; dy = sgy[n+1]-sgy[n];
            sginv[n] = 1.0f / fmaxf(dx*dx+dy*dy, 1e-8f);
        }
        __syncthreads();

        float qx = spx[n], qy = spy[n], ux = sgx[n], uy = sgy[n];
        float da2 = BIG2, db2 = BIG2;
        #pragma unroll 3
        for (int s = 0; s < NRS-1; s++) {
            {
                float ax = sgx[s], ay = sgy[s];
                float abx = sgx[s+1]-ax, aby = sgy[s+1]-ay;
                float t = ((qx-ax)*abx + (qy-ay)*aby) * sginv[s];
                t = fminf(fmaxf(t, 0.f), 1.f);
                float dx = qx - ax - t*abx, dy = qy - ay - t*aby;
                da2 = fminf(da2, dx*dx + dy*dy);
            }
            {
                float ax = spx[s], ay = spy[s];
                float abx = spx[s+1]-ax, aby = spy[s+1]-ay;
                float t = ((ux-ax)*abx + (uy-ay)*aby) * spinv[s];
                t = fminf(fmaxf(t, 0.f), 1.f);
                float dx = ux - ax - t*abx, dy = uy - ay - t*aby;
                db2 = fminf(db2, dx*dx + dy*dy);
            }
        }
        float dd = sqrtf(da2) + sqrtf(db2);

        const float* pt  = g_ptan + (b*MP+i)*NRS*2;
        const float* gtt = g_gtan + (b*MG+j)*NRS*2;
        float td = fabsf(pt[2*n]*gtt[2*n] + pt[2*n+1]*gtt[2*n+1]);

        float cv = 0.f;
        if (n < NRS-2) {
            float psx = spx[n+2] - 2.f*spx[n+1] + spx[n];
            float psy = spy[n+2] - 2.f*spy[n+1] + spy[n];
            float gsx = sgx[n+2] - 2.f*sgx[n+1] + sgx[n];
            float gsy = sgy[n+2] - 2.f*sgy[n+1] + sgy[n];
            cv = sl1(psx-gsx) + sl1(psy-gsy);
        }
        unsigned m = 0xffffffffu;
        #pragma unroll
        for (int o = 16; o; o >>= 1) {
            dd += __shfl_down_sync(m, dd, o);
            td += __shfl_down_sync(m, td, o);
            cv += __shfl_down_sync(m, cv, o);
        }
        int w = (n >> 5), l = n & 31;
        if (l == 0) { red[w*3+0]=dd; red[w*3+1]=td; red[w*3+2]=cv; }
        __syncthreads();
        if (n == 0) {
            float sdd = red[0] + red[3];
            float std_ = red[1] + red[4];
            float scv = red[2] + red[5];
            float sym  = 0.5f * sdd * (1.0f/NRS);
            float tanv = 1.0f - std_ * (1.0f/NRS);
            float curv = scv * (1.0f/((NRS-2)*2));
            g_partial[pid] = 5.0f*sym + 1.0f*tanv + 0.5f*curv;
        }
    } else {
        // ---------------- IoU over grid chunk ----------------
        int blk = bid - 480;
        int b  = blk / 144;
        int ch = blk % 144;
        int gbase = ch * 64;

        for (int idx = tid; idx < 64*64; idx += 256) {
            int c = idx >> 6, g = idx & 63;
            float v = (c < MP) ? g_pmask[(b*MP + c)*GRID_N + gbase + g]
                               : g_gmask[(b*MG + (c-MP))*GRID_N + gbase + g];
            sm[c*68 + g] = v;
        }
        __syncthreads();

        for (int p = tid; p < MP*MG; p += 256) {
            int i = p / MG, j = p % MG;
            const float4* ar = (const float4*)(sm + i*68);
            const float4* br = (const float4*)(sm + (MP+j)*68);
            float si = 0.f, su = 0.f;
            #pragma unroll
            for (int q = 0; q < 16; q++) {
                float4 a = ar[q], bb = br[q];
                si += fminf(a.x,bb.x) + fminf(a.y,bb.y) + fminf(a.z,bb.z) + fminf(a.w,bb.w);
                su += fmaxf(a.x,bb.x) + fmaxf(a.y,bb.y) + fmaxf(a.z,bb.z) + fmaxf(a.w,bb.w);
            }
            atomicAdd(&g_inter[b*MP*MG + p], si);
            atomicAdd(&g_uni  [b*MP*MG + p], su);
        }
    }
}

// =====================================================================
// Kernel C: combine + exist mask
// =====================================================================
__global__ void k_final(const float* __restrict__ exist, float* __restrict__ out) {
    int p = blockIdx.x*256 + threadIdx.x;
    if (p < NPAIR) {
        int b = p / (MP*MG);
        int j = p % MG;
        float ov = 1.0f - g_inter[p] / (g_uni[p] + 1e-8f);
        float cost = g_partial[p] + 2.0f*ov;
        out[p] = (exist[b*MG + j] > 0.5f) ? cost : 0.0f;
    }
}

// ---------------- launch ----------------
extern "C" void kernel_launch(void* const* d_in, const int* in_sizes, int n_in,
                              void* d_out, int out_size) {
    const float* pred  = (const float*)d_in[0];
    const float* gt    = (const float*)d_in[1];
    const float* vis   = (const float*)d_in[2];
    const float* exist = (const float*)d_in[3];
    float* out = (float*)d_out;

    k_A<<<1280, 256>>>(pred, gt, vis);
    k_B<<<768, 256>>>();
    k_final<<<(NPAIR + 255)/256, 256>>>(exist, out);
}

// round 4
// speedup vs baseline: 3.1213x; 1.1146x over previous
#include <cuda_runtime.h>
#include <math.h>

#define BATCH 2
#define MP 40
#define MG 24
#define NPT 24
#define NRS 64
#define Hh 72
#define Ww 128
#define GRID_N (Hh*Ww)      // 9216
#define NPAIR (BATCH*MP*MG) // 1920
#define BIG2 1e18f
#define THICKF 0.03f
#define SHARPF 80.0f

// ---------------- device scratch ----------------
__device__ float g_prs [BATCH*MP*NRS*2];
__device__ float g_grs [BATCH*MG*NRS*2];
__device__ float g_ptan[BATCH*MP*NRS*2];
__device__ float g_gtan[BATCH*MG*NRS*2];
__device__ float g_pmask[BATCH*MP*GRID_N];
__device__ float g_gmask[BATCH*MG*GRID_N];
__device__ float g_partial[NPAIR];
__device__ float g_inter[NPAIR];
__device__ float g_uni[NPAIR];

__device__ __forceinline__ float sl1(float d) {
    d = fabsf(d);
    return d < 1.f ? 0.5f*d*d : d - 0.5f;
}

// =====================================================================
// Kernel A (128 threads/block):
//   blocks 0..127:    resample + tangents (one curve per block)
//   blocks 128..1279: soft masks; curve=(bid-128)/9, chunk=(bid-128)%9.
//                     Each thread owns one grid COLUMN x (tid), 8 rows.
//   also zeroes the inter/union accumulators
// =====================================================================
__global__ void __launch_bounds__(128, 8)
k_A(const float* __restrict__ pred,
    const float* __restrict__ gt,
    const float* __restrict__ vis) {
    int bid = blockIdx.x, tid = threadIdx.x;
    int gtid = bid*128 + tid;
    if (gtid < NPAIR) { g_inter[gtid] = 0.f; g_uni[gtid] = 0.f; }

    if (bid < 128) {
        // ---------------- resample + tangents ----------------
        __shared__ float px[NPT], py[NPT], pm[NPT], cum[NPT];
        __shared__ float ox[NRS], oy[NRS];
        int cid = bid;
        bool isPred = cid < BATCH*MP;
        const float* src; float *dst_rs, *dst_tan; int b, c;
        if (isPred) {
            b = cid / MP; c = cid % MP;
            src = pred + (b*MP + c)*NPT*2;
            dst_rs  = g_prs  + (b*MP + c)*NRS*2;
            dst_tan = g_ptan + (b*MP + c)*NRS*2;
        } else {
            int q = cid - BATCH*MP;
            b = q / MG; c = q % MG;
            src = gt + (b*MG + c)*NPT*2;
            dst_rs  = g_grs  + (b*MG + c)*NRS*2;
            dst_tan = g_gtan + (b*MG + c)*NRS*2;
        }
        if (tid < NPT) {
            px[tid] = src[tid*2];
            py[tid] = src[tid*2+1];
            pm[tid] = isPred ? 1.0f : (vis[(b*MG+c)*NPT + tid] > 0.5f ? 1.0f : 0.0f);
        }
        __syncthreads();
        if (tid == 0) {
            if (!isPred) {
                int cnt = 0;
                for (int k = 0; k < NPT; k++) cnt += (pm[k] > 0.5f);
                if (cnt < 2) for (int k = 0; k < NPT; k++) pm[k] = 1.0f;
            }
            float s = 0.f; cum[0] = 0.f;
            for (int k = 0; k < NPT-1; k++) {
                float dx = px[k+1]-px[k], dy = py[k+1]-py[k];
                s += sqrtf(dx*dx+dy*dy) * (pm[k]*pm[k+1]);
                cum[k+1] = s;
            }
        }
        __syncthreads();
        if (tid < NRS) {
            float total = cum[NPT-1];
            float qx, qy;
            if (total < 1e-8f) { qx = px[0]; qy = py[0]; }
            else {
                float t = (tid == NRS-1) ? total : tid * (1.0f/(NRS-1)) * total;
                int cnt = 0;
                for (int k = 0; k < NPT; k++) cnt += (cum[k] <= t);
                int idx = cnt - 1;
                if (idx > NPT-2) idx = NPT-2;
                if (idx < 0)     idx = 0;
                float lt = cum[idx], rt = cum[idx+1];
                float alpha = (t - lt) / fmaxf(rt - lt, 1e-8f);
                qx = px[idx] + alpha*(px[idx+1]-px[idx]);
                qy = py[idx] + alpha*(py[idx+1]-py[idx]);
            }
            ox[tid] = qx; oy[tid] = qy;
            dst_rs[tid*2]   = qx;
            dst_rs[tid*2+1] = qy;
        }
        __syncthreads();
        if (tid < NRS) {
            int a = (tid == 0)     ? 0     : tid-1;
            int e = (tid == NRS-1) ? NRS-1 : tid+1;
            float fx = ox[e]-ox[a], fy = oy[e]-oy[a];
            float nr = fmaxf(sqrtf(fx*fx+fy*fy), 1e-8f);
            dst_tan[tid*2]   = fx/nr;
            dst_tan[tid*2+1] = fy/nr;
        }
    } else {
        // ---------------- soft mask: column-constant X, 8 rows/thread ----------------
        int mb = bid - 128;
        int cid = mb / 9, chunk = mb % 9;
        __shared__ float px[NPT], py[NPT], pm[NPT], sppen[NPT];
        __shared__ __align__(16) float4 s4a[NPT-1];   // ax, ay, abx, aby
        __shared__ __align__(16) float4 s4b[NPT-1];   // bx, by, c, pen
        __shared__ int s_any;

        bool isPred = cid < BATCH*MP;
        const float* src; float* dst; int b, c;
        if (isPred) {
            b = cid/MP; c = cid%MP;
            src = pred + (b*MP+c)*NPT*2;
            dst = g_pmask + (b*MP+c)*GRID_N;
        } else {
            int q = cid - BATCH*MP;
            b = q/MG; c = q%MG;
            src = gt + (b*MG+c)*NPT*2;
            dst = g_gmask + (b*MG+c)*GRID_N;
        }
        if (tid < NPT) {
            px[tid] = src[tid*2];
            py[tid] = src[tid*2+1];
            pm[tid] = isPred ? 1.f : (vis[(b*MG+c)*NPT+tid] > 0.5f ? 1.f : 0.f);
        }
        __syncthreads();
        if (tid == 0) {
            if (!isPred) {
                int cnt = 0;
                for (int k = 0; k < NPT; k++) cnt += (pm[k] > 0.5f);
                if (cnt < 2) for (int k = 0; k < NPT; k++) pm[k] = 1.f;
            }
            int any = 0;
            for (int k = 0; k < NPT-1; k++) any |= (pm[k]*pm[k+1] > 0.5f);
            s_any = any;
        }
        __syncthreads();
        if (tid < NPT-1) {
            float ax = px[tid], ay = py[tid];
            float abx = px[tid+1]-ax, aby = py[tid+1]-ay;
            float inv = 1.0f / fmaxf(abx*abx + aby*aby, 1e-8f);
            s4a[tid] = make_float4(ax, ay, abx, aby);
            s4b[tid] = make_float4(abx*inv, aby*inv, (ax*abx + ay*aby)*inv,
                                   (pm[tid]*pm[tid+1] > 0.5f) ? 0.f : BIG2);
        }
        if (tid < NPT) sppen[tid] = (pm[tid] > 0.5f) ? 0.f : BIG2;
        __syncthreads();

        float X = tid * (1.0f/(Ww-1));
        int row0 = chunk*8;
        float m[8];
        #pragma unroll
        for (int k = 0; k < 8; k++) m[k] = BIG2;

        if (s_any) {
            #pragma unroll 1
            for (int s = 0; s < NPT-1; s++) {
                float4 A = s4a[s];
                float4 B = s4b[s];
                float e   = fmaf(X, B.x, -B.z);       // X*bx - c
                float dxs = X - A.x;                  // shared over rows
                float sxp = fmaf(dxs, dxs, 0.f);      // dxs^2
                #pragma unroll
                for (int k = 0; k < 8; k++) {
                    float Y = (row0 + k) * (1.0f/(Hh-1));
                    float t = fmaf(Y, B.y, e);        // = ((X-ax)*abx+(Y-ay)*aby)*inv
                    t = fminf(fmaxf(t, 0.f), 1.f);
                    float dx = fmaf(-t, A.z, dxs);
                    float dy = fmaf(-t, A.w, Y - A.y);
                    float d2 = fmaf(dy, dy, fmaf(dx, dx, B.w));
                    m[k] = fminf(m[k], d2);
                }
                (void)sxp;
            }
        } else {
            #pragma unroll 1
            for (int p = 0; p < NPT; p++) {
                float ax = px[p], ay = py[p], pen = sppen[p];
                float dxs = X - ax;
                float sxp = fmaf(dxs, dxs, pen);
                #pragma unroll
                for (int k = 0; k < 8; k++) {
                    float dy = (row0 + k) * (1.0f/(Hh-1)) - ay;
                    m[k] = fminf(m[k], fmaf(dy, dy, sxp));
                }
            }
        }
        int base = chunk*1024 + tid;
        #pragma unroll
        for (int k = 0; k < 8; k++) {
            float z = (THICKF - sqrtf(m[k])) * SHARPF;
            dst[base + 128*k] = __fdividef(1.0f, 1.0f + __expf(-z));
        }
    }
}

// =====================================================================
// Kernel B: [blocks 0..479]   pairwise sym/tan/curv (4 pairs per block)
//           [blocks 480..767] IoU accumulation over 64-pt grid chunks
// =====================================================================
#define GSTRIDE 1272
__global__ void __launch_bounds__(256, 4)
k_B() {
    __shared__ __align__(16) float sm[4*GSTRIDE];   // 20352 B (>= 64*68 for IoU half)
    int bid = blockIdx.x, tid = threadIdx.x;

    if (bid < 480) {
        // ---------------- pair costs ----------------
        int grp = tid >> 6, n = tid & 63;
        int pid = bid*4 + grp;
        int b = pid / (MP*MG);
        int r = pid % (MP*MG);
        int i = r / MG, j = r % MG;

        float* gp  = sm + grp*GSTRIDE;
        float* spx = gp;        float* spy = gp + 64;
        float* sgx = gp + 128;  float* sgy = gp + 192;
        float4* psa = (float4*)(gp + 256);   // pred segs: ax,ay,abx,aby
        float4* psb = (float4*)(gp + 508);   // pred segs: bx,by,c,0
        float4* gsa = (float4*)(gp + 760);
        float4* gsb = (float4*)(gp + 1012);
        float* red  = gp + 1264;             // 6 floats

        const float* pr = g_prs + (b*MP+i)*NRS*2;
        const float* gr = g_grs + (b*MG+j)*NRS*2;
        spx[n] = pr[2*n]; spy[n] = pr[2*n+1];
        sgx[n] = gr[2*n]; sgy[n] = gr[2*n+1];
        __syncthreads();
        if (n < NRS-1) {
            float ax = spx[n], ay = spy[n];
            float abx = spx[n+1]-ax, aby = spy[n+1]-ay;
            float inv = 1.0f / fmaxf(abx*abx+aby*aby, 1e-8f);
            psa[n] = make_float4(ax, ay, abx, aby);
            psb[n] = make_float4(abx*inv, aby*inv, (ax*abx+ay*aby)*inv, 0.f);
            ax = sgx[n]; ay = sgy[n];
            abx = sgx[n+1]-ax; aby = sgy[n+1]-ay;
            inv = 1.0f / fmaxf(abx*abx+aby*aby, 1e-8f);
            gsa[n] = make_float4(ax, ay, abx, aby);
            gsb[n] = make_float4(abx*inv, aby*inv, (ax*abx+ay*aby)*inv, 0.f);
        }
        __syncthreads();

        float qx = spx[n], qy = spy[n], ux = sgx[n], uy = sgy[n];
        float da2 = BIG2, db2 = BIG2;
        #pragma unroll 3
        for (int s = 0; s < NRS-1; s++) {
            {
                float4 A = gsa[s], B = gsb[s];
                float t = fmaf(qy, B.y, fmaf(qx, B.x, -B.z));
                t = fminf(fmaxf(t, 0.f), 1.f);
                float dx = fmaf(-t, A.z, qx - A.x);
                float dy = fmaf(-t, A.w, qy - A.y);
                da2 = fminf(da2, fmaf(dy, dy, dx*dx));
            }
            {
                float4 A = psa[s], B = psb[s];
                float t = fmaf(uy, B.y, fmaf(ux, B.x, -B.z));
                t = fminf(fmaxf(t, 0.f), 1.f);
                float dx = fmaf(-t, A.z, ux - A.x);
                float dy = fmaf(-t, A.w, uy - A.y);
                db2 = fminf(db2, fmaf(dy, dy, dx*dx));
            }
        }
        float dd = sqrtf(da2) + sqrtf(db2);

        const float* pt  = g_ptan + (b*MP+i)*NRS*2;
        const float* gtt = g_gtan + (b*MG+j)*NRS*2;
        float td = fabsf(pt[2*n]*gtt[2*n] + pt[2*n+1]*gtt[2*n+1]);

        float cv = 0.f;
        if (n < NRS-2) {
            float psx = spx[n+2] - 2.f*spx[n+1] + spx[n];
            float psy = spy[n+2] - 2.f*spy[n+1] + spy[n];
            float gsxv = sgx[n+2] - 2.f*sgx[n+1] + sgx[n];
            float gsyv = sgy[n+2] - 2.f*sgy[n+1] + sgy[n];
            cv = sl1(psx-gsxv) + sl1(psy-gsyv);
        }
        unsigned msk = 0xffffffffu;
        #pragma unroll
        for (int o = 16; o; o >>= 1) {
            dd += __shfl_down_sync(msk, dd, o);
            td += __shfl_down_sync(msk, td, o);
            cv += __shfl_down_sync(msk, cv, o);
        }
        int w = (n >> 5), l = n & 31;
        if (l == 0) { red[w*3+0]=dd; red[w*3+1]=td; red[w*3+2]=cv; }
        __syncthreads();
        if (n == 0) {
            float sdd  = red[0] + red[3];
            float std_ = red[1] + red[4];
            float scv  = red[2] + red[5];
            float sym  = 0.5f * sdd * (1.0f/NRS);
            float tanv = 1.0f - std_ * (1.0f/NRS);
            float curv = scv * (1.0f/((NRS-2)*2));
            g_partial[pid] = 5.0f*sym + 1.0f*tanv + 0.5f*curv;
        }
    } else {
        // ---------------- IoU over grid chunk ----------------
        int blk = bid - 480;
        int b  = blk / 144;
        int ch = blk % 144;
        int gbase = ch * 64;

        for (int idx = tid; idx < 64*64; idx += 256) {
            int c = idx >> 6, g = idx & 63;
            float v = (c < MP) ? g_pmask[(b*MP + c)*GRID_N + gbase + g]
                               : g_gmask[(b*MG + (c-MP))*GRID_N + gbase + g];
            sm[c*68 + g] = v;
        }
        __syncthreads();

        for (int p = tid; p < MP*MG; p += 256) {
            int i = p / MG, j = p % MG;
            const float4* ar = (const float4*)(sm + i*68);
            const float4* br = (const float4*)(sm + (MP+j)*68);
            float si = 0.f, su = 0.f;
            #pragma unroll
            for (int q = 0; q < 16; q++) {
                float4 a = ar[q], bb = br[q];
                si += fminf(a.x,bb.x) + fminf(a.y,bb.y) + fminf(a.z,bb.z) + fminf(a.w,bb.w);
                su += fmaxf(a.x,bb.x) + fmaxf(a.y,bb.y) + fmaxf(a.z,bb.z) + fmaxf(a.w,bb.w);
            }
            atomicAdd(&g_inter[b*MP*MG + p], si);
            atomicAdd(&g_uni  [b*MP*MG + p], su);
        }
    }
}

// =====================================================================
// Kernel C: combine + exist mask
// =====================================================================
__global__ void k_final(const float* __restrict__ exist, float* __restrict__ out) {
    int p = blockIdx.x*256 + threadIdx.x;
    if (p < NPAIR) {
        int b = p / (MP*MG);
        int j = p % MG;
        float ov = 1.0f - g_inter[p] / (g_uni[p] + 1e-8f);
        float cost = g_partial[p] + 2.0f*ov;
        out[p] = (exist[b*MG + j] > 0.5f) ? cost : 0.0f;
    }
}

// ---------------- launch ----------------
extern "C" void kernel_launch(void* const* d_in, const int* in_sizes, int n_in,
                              void* d_out, int out_size) {
    const float* pred  = (const float*)d_in[0];
    const float* gt    = (const float*)d_in[1];
    const float* vis   = (const float*)d_in[2];
    const float* exist = (const float*)d_in[3];
    float* out = (float*)d_out;

    k_A<<<1280, 128>>>(pred, gt, vis);
    k_B<<<768, 256>>>();
    k_final<<<(NPAIR + 255)/256, 256>>>(exist, out);
}